// round 6
// baseline (speedup 1.0000x reference)
#include <cuda_runtime.h>
#include <cuda_bf16.h>
#include <cstdint>

#define BB 4
#define CC 19
#define HH 512
#define WW 1024
#define HW (HH * WW)            // 524288 = 2^19
#define NPIX (BB * HW)          // 2097152
#define NBC (BB * CC)           // 76

#define RAWB  160               // raw bins: (u>>18) - BASE1
#define BASE1 0xF50u            // u>>18 in [0xF55, 0xFE0] for p in (1/19, 1]
#define SPLIT 137               // raw bin containing p = 0.9 (0xFD9 - 0xF50)
#define LBINS 161               // logical bins (SPLIT bin split at exactly 0.9)
#define HI0   138               // first logical bin with p > 0.9 everywhere
#define U09   0x3F666666u       // bits(0.9f); p > 0.9  <=>  u > U09

#define NBLK_C 512              // compute blocks: 128 per image, 4096 px each
#define CHUNKS 4                // 4 chunks x 256 threads x 4 px = 4096 px

// ---------------- device scratch (static, zero-init at load) ----------------
__device__ unsigned int g_cnt[NBC * LBINS];    // per-bin pixel counts
__device__ float        g_sum[NBC * LBINS];    // per-bin exact nll sums
__device__ float        g_loss[NBC];
__device__ unsigned int g_done;

// ---------------- 2-barrier suffix scans (suf[t] = sum over bins >= t) ------
__device__ __forceinline__ unsigned suffix_scan(unsigned v, int t, int nwarps,
                                                unsigned* wsum) {
    unsigned lane = t & 31, w = (unsigned)t >> 5;
    unsigned x = v;
#pragma unroll
    for (int d = 1; d < 32; d <<= 1) {
        unsigned y = __shfl_down_sync(0xFFFFFFFFu, x, d);
        if (lane + d < 32) x += y;
    }
    if (lane == 0) wsum[w] = x;
    __syncthreads();
    if (w == 0) {
        unsigned wv = (lane < (unsigned)nwarps) ? wsum[lane] : 0u;
        unsigned own = wv;
#pragma unroll
        for (int d = 1; d < 32; d <<= 1) {
            unsigned y = __shfl_down_sync(0xFFFFFFFFu, wv, d);
            if (lane + d < 32) wv += y;
        }
        if (lane < (unsigned)nwarps) wsum[lane] = wv - own;   // exclusive suffix
    }
    __syncthreads();
    return x + wsum[w];
}

__device__ __forceinline__ float suffix_scanf(float v, int t, int nwarps,
                                              float* wsum) {
    unsigned lane = t & 31, w = (unsigned)t >> 5;
    float x = v;
#pragma unroll
    for (int d = 1; d < 32; d <<= 1) {
        float y = __shfl_down_sync(0xFFFFFFFFu, x, d);
        if (lane + d < 32) x += y;
    }
    if (lane == 0) wsum[w] = x;
    __syncthreads();
    if (w == 0) {
        float wv = (lane < (unsigned)nwarps) ? wsum[lane] : 0.f;
        float own = wv;
#pragma unroll
        for (int d = 1; d < 32; d <<= 1) {
            float y = __shfl_down_sync(0xFFFFFFFFu, wv, d);
            if (lane + d < 32) wv += y;
        }
        if (lane < (unsigned)nwarps) wsum[lane] = wv - own;
    }
    __syncthreads();
    return x + wsum[w];
}

// ---------------- main: online softmax + (count, nll-sum) histogram ---------
#define UPD(V, MX, S, AM, C)                                                   \
    if ((V) > (MX)) { (S) = (S) * __expf((MX) - (V)) + 1.0f; (MX) = (V); (AM) = (C); } \
    else            { (S) += __expf((V) - (MX)); }

__global__ void __launch_bounds__(256) k_compute(const float* __restrict__ pred) {
    __shared__ unsigned scnt[CC * LBINS];       // 12.2 KB
    __shared__ float    ssum[CC * LBINS];       // 12.2 KB
    unsigned tx = threadIdx.x;
    unsigned b  = blockIdx.x >> 7;              // 128 blocks per image
    unsigned nb = (blockIdx.x & 127u) * (CHUNKS * 1024u);

    for (int i = tx; i < CC * LBINS; i += 256) { scnt[i] = 0; ssum[i] = 0.f; }
    __syncthreads();

    const float* img = pred + (size_t)b * CC * HW;
    const unsigned cs = HW / 4;

#pragma unroll
    for (int ch = 0; ch < CHUNKS; ch++) {
        unsigned n = nb + (unsigned)ch * 1024u + tx * 4u;
        const float4* base = reinterpret_cast<const float4*>(img + n);

        float4 x = __ldg(base);
        float m0 = x.x, m1 = x.y, m2 = x.z, m3 = x.w;
        float s0 = 1.f, s1 = 1.f, s2 = 1.f, s3 = 1.f;
        int   a0 = 0, a1 = 0, a2 = 0, a3 = 0;

#pragma unroll
        for (int c = 1; c < CC; c++) {
            float4 v = __ldg(base + (size_t)c * cs);
            UPD(v.x, m0, s0, a0, c);
            UPD(v.y, m1, s1, a1, c);
            UPD(v.z, m2, s2, a2, c);
            UPD(v.w, m3, s3, a3, c);
        }

#define DEPOSIT(S, A) {                                                        \
        float nll = __logf(S);                  /* == -log(max_prob) */        \
        unsigned u = __float_as_uint(1.0f / (S));                              \
        int raw = (int)(u >> 18) - (int)BASE1;                                 \
        raw = raw < 0 ? 0 : (raw > RAWB - 1 ? RAWB - 1 : raw);                 \
        int lb = raw < SPLIT ? raw                                             \
               : (raw == SPLIT ? (SPLIT + (u > U09 ? 1 : 0)) : raw + 1);       \
        int idx = (A) * LBINS + lb;                                            \
        atomicAdd(&scnt[idx], 1u);                                             \
        atomicAdd(&ssum[idx], nll); }
        DEPOSIT(s0, a0); DEPOSIT(s1, a1); DEPOSIT(s2, a2); DEPOSIT(s3, a3);
#undef DEPOSIT
    }
    __syncthreads();

    for (int i = tx; i < CC * LBINS; i += 256) {
        unsigned c = scnt[i];
        if (c) {
            atomicAdd(&g_cnt[b * (CC * LBINS) + i], c);
            atomicAdd(&g_sum[b * (CC * LBINS) + i], ssum[i]);
        }
    }
}

// ---------------- finish: per-(b,c) loss from histogram + fused scalar ------
__global__ void __launch_bounds__(256) k_finish(float* __restrict__ out) {
    __shared__ unsigned sufc_sh[257];
    __shared__ float    suff_sh[257];
    __shared__ unsigned wsc[32];
    __shared__ float    wsf[32];
    __shared__ float    sloss;
    __shared__ bool     last;
    int bc = blockIdx.x;
    int t  = threadIdx.x;

    unsigned cnt = 0; float sm = 0.f;
    if (t < LBINS) {
        cnt = g_cnt[bc * LBINS + t];
        sm  = g_sum[bc * LBINS + t];
        g_cnt[bc * LBINS + t] = 0;              // clean for next graph replay
        g_sum[bc * LBINS + t] = 0.f;
    }
    if (t == 0) { sloss = 0.f; sufc_sh[256] = 0; suff_sh[256] = 0.f; }

    unsigned sc = suffix_scan(cnt, t, 8, wsc);
    float    sf = suffix_scanf(sm, t, 8, wsf);
    sufc_sh[t] = sc;                            // t >= LBINS naturally 0
    suff_sh[t] = sf;
    __syncthreads();

    unsigned tot = sufc_sh[0];
    unsigned k = (unsigned)floorf((float)tot * 0.66f);

    if (k == 0) {
        if (t == 0) sloss = suff_sh[HI0];       // prob-mask only
    } else if (t < LBINS) {
        unsigned nxt = sufc_sh[t + 1];
        if (sc >= k && nxt < k) {               // unique threshold bin T = t
            float loss;
            if (t >= HI0) loss = suff_sh[HI0];  // all hi pixels kept (mask OR)
            else {
                unsigned m = k - nxt;           // kept pixels inside bin T
                loss = suff_sh[t + 1] + (float)m * (sm / (float)cnt);
            }
            sloss = loss;
        }
    }
    __syncthreads();

    if (t == 0) {
        g_loss[bc] = sloss;
        __threadfence();
        last = (atomicAdd(&g_done, 1u) == NBC - 1);
    }
    __syncthreads();

    if (last) {                                  // deterministic final reduce
        __shared__ double dred[256];
        dred[t] = (t < NBC) ? (double)g_loss[t] : 0.0;
        __syncthreads();
#pragma unroll
        for (int s = 128; s > 0; s >>= 1) {
            if (t < s) dred[t] += dred[t + s];
            __syncthreads();
        }
        if (t == 0) {
            out[0] = (float)(dred[0] * (1.0 / (double)NPIX));
            g_done = 0;                          // reset for next replay
        }
    }
}

// ---------------- launcher ---------------------------------------------------
extern "C" void kernel_launch(void* const* d_in, const int* in_sizes, int n_in,
                              void* d_out, int out_size) {
    const float* pred = (const float*)d_in[0];
    float* out = (float*)d_out;
    (void)in_sizes; (void)n_in; (void)out_size;

    k_compute<<<NBLK_C, 256>>>(pred);
    k_finish<<<NBC, 256>>>(out);
}

// round 7
// speedup vs baseline: 1.0004x; 1.0004x over previous
#include <cuda_runtime.h>
#include <cuda_bf16.h>
#include <cstdint>

#define BB 4
#define CC 19
#define HW (512 * 1024)         // 524288
#define NPIX (BB * HW)          // 2097152
#define NBC (BB * CC)           // 76

// s = sum(exp(x - max)) in [1, 19]; bin on s-bits (monotone-inverse of p).
#define RAWB  135               // raw bins: (bits(s)>>18) - 0xFE0, clamped
#define BASES 0xFE0u            // bits(1.0f) >> 18
#define US09  0x3F8E38E4u       // bits(float(1/0.9)); p>0.9 <=> bits(s) < US09
#define LBINS 136               // p-ascending logical bins, raw bin 3 split at 1/0.9
#define HI0   132               // first logical bin with p > 0.9 everywhere
#define QS    32.0f             // nll quantization scale (q = rn(nll*32) <= 95)

#define NBLK_C 1024             // 256 blocks/image, 2048 px per block
#define CHUNKS 2

// ---------------- device scratch (static, zero-init at load) ----------------
__device__ unsigned long long g_hist[NBC * LBINS];  // (count<<32) | qsum
__device__ float              g_loss[NBC];
__device__ unsigned int       g_done;

// ---------------- 2-barrier suffix scans (suf[t] = sum over bins >= t) ------
__device__ __forceinline__ unsigned suffix_scan(unsigned v, int t, int nwarps,
                                                unsigned* wsum) {
    unsigned lane = t & 31, w = (unsigned)t >> 5;
    unsigned x = v;
#pragma unroll
    for (int d = 1; d < 32; d <<= 1) {
        unsigned y = __shfl_down_sync(0xFFFFFFFFu, x, d);
        if (lane + d < 32) x += y;
    }
    if (lane == 0) wsum[w] = x;
    __syncthreads();
    if (w == 0) {
        unsigned wv = (lane < (unsigned)nwarps) ? wsum[lane] : 0u;
        unsigned own = wv;
#pragma unroll
        for (int d = 1; d < 32; d <<= 1) {
            unsigned y = __shfl_down_sync(0xFFFFFFFFu, wv, d);
            if (lane + d < 32) wv += y;
        }
        if (lane < (unsigned)nwarps) wsum[lane] = wv - own;   // exclusive suffix
    }
    __syncthreads();
    return x + wsum[w];
}

__device__ __forceinline__ float suffix_scanf(float v, int t, int nwarps,
                                              float* wsum) {
    unsigned lane = t & 31, w = (unsigned)t >> 5;
    float x = v;
#pragma unroll
    for (int d = 1; d < 32; d <<= 1) {
        float y = __shfl_down_sync(0xFFFFFFFFu, x, d);
        if (lane + d < 32) x += y;
    }
    if (lane == 0) wsum[w] = x;
    __syncthreads();
    if (w == 0) {
        float wv = (lane < (unsigned)nwarps) ? wsum[lane] : 0.f;
        float own = wv;
#pragma unroll
        for (int d = 1; d < 32; d <<= 1) {
            float y = __shfl_down_sync(0xFFFFFFFFu, wv, d);
            if (lane + d < 32) wv += y;
        }
        if (lane < (unsigned)nwarps) wsum[lane] = wv - own;
    }
    __syncthreads();
    return x + wsum[w];
}

// ---------------- main: branchless online softmax + packed histogram --------
// single exp per element: e = exp(-|v-mx|); rescale path uses same e.
#define UPD(V, MX, S, AM, C) {                                                 \
        float d_ = (V) - (MX);                                                 \
        float e_ = __expf(0.0f - fabsf(d_));                                   \
        bool  g_ = d_ > 0.0f;                                                  \
        (S)  = g_ ? __fmaf_rn((S), e_, 1.0f) : ((S) + e_);                     \
        (MX) = g_ ? (V) : (MX);                                                \
        (AM) = g_ ? (C) : (AM); }

__global__ void __launch_bounds__(256) k_compute(const float* __restrict__ pred) {
    __shared__ unsigned shist[CC * LBINS];      // 10.3 KB
    unsigned tx = threadIdx.x;
    unsigned b  = blockIdx.x >> 8;              // 256 blocks per image
    unsigned nb = (blockIdx.x & 255u) * (CHUNKS * 1024u);

    for (int i = tx; i < CC * LBINS; i += 256) shist[i] = 0;
    __syncthreads();

    const float* img = pred + (size_t)b * CC * HW;
    const unsigned cs = HW / 4;

#pragma unroll
    for (int ch = 0; ch < CHUNKS; ch++) {
        unsigned n = nb + (unsigned)ch * 1024u + tx * 4u;
        const float4* base = reinterpret_cast<const float4*>(img + n);

        float4 x = __ldg(base);
        float m0 = x.x, m1 = x.y, m2 = x.z, m3 = x.w;
        float s0 = 1.f, s1 = 1.f, s2 = 1.f, s3 = 1.f;
        int   a0 = 0, a1 = 0, a2 = 0, a3 = 0;

#pragma unroll
        for (int c = 1; c < CC; c++) {
            float4 v = __ldg(base + (size_t)c * cs);
            UPD(v.x, m0, s0, a0, c);
            UPD(v.y, m1, s1, a1, c);
            UPD(v.z, m2, s2, a2, c);
            UPD(v.w, m3, s3, a3, c);
        }

        // deposit: one u32 atomic per pixel, count in bits 19.., qsum in 0..18
#define DEPOSIT(S, A) {                                                        \
        float nll = __logf(S);                                                 \
        unsigned q = __float2uint_rn(nll * QS);         /* <= 95 */            \
        unsigned us = __float_as_uint(S);                                      \
        int raw = (int)(us >> 18) - (int)BASES;                                \
        raw = raw < 0 ? 0 : (raw > RAWB - 1 ? RAWB - 1 : raw);                 \
        int lb = raw > 3 ? 134 - raw                                           \
               : (raw == 3 ? (us < US09 ? 132 : 131) : 135 - raw);             \
        atomicAdd(&shist[(A) * LBINS + lb], (1u << 19) | q); }
        DEPOSIT(s0, a0); DEPOSIT(s1, a1); DEPOSIT(s2, a2); DEPOSIT(s3, a3);
#undef DEPOSIT
    }
    __syncthreads();

    for (int i = tx; i < CC * LBINS; i += 256) {
        unsigned v = shist[i];
        if (v)
            atomicAdd(&g_hist[b * (CC * LBINS) + i],
                      ((unsigned long long)(v >> 19) << 32) |
                       (unsigned long long)(v & 0x7FFFFu));
    }
}

// ---------------- finish: per-(b,c) loss from histogram + fused scalar ------
__global__ void __launch_bounds__(256) k_finish(float* __restrict__ out) {
    __shared__ unsigned sufc_sh[257];
    __shared__ float    suff_sh[257];
    __shared__ unsigned wsc[32];
    __shared__ float    wsf[32];
    __shared__ float    sloss;
    __shared__ bool     last;
    int bc = blockIdx.x;
    int t  = threadIdx.x;

    unsigned cnt = 0; float qf = 0.f;
    if (t < LBINS) {
        unsigned long long h = g_hist[bc * LBINS + t];
        cnt = (unsigned)(h >> 32);
        qf  = (float)(unsigned)(h & 0xFFFFFFFFull);
        g_hist[bc * LBINS + t] = 0ull;          // clean for next graph replay
    }
    if (t == 0) { sloss = 0.f; sufc_sh[256] = 0; suff_sh[256] = 0.f; }

    unsigned sc = suffix_scan(cnt, t, 8, wsc);
    float    sf = suffix_scanf(qf, t, 8, wsf);
    sufc_sh[t] = sc;
    suff_sh[t] = sf;
    __syncthreads();

    unsigned tot = sufc_sh[0];
    unsigned k = (unsigned)floorf((float)tot * 0.66f);

    if (k == 0) {
        if (t == 0) sloss = suff_sh[HI0];       // prob-mask only
    } else if (t < LBINS) {
        unsigned nxt = sufc_sh[t + 1];
        if (sc >= k && nxt < k) {               // unique threshold bin T = t
            float loss;
            if (t >= HI0) loss = suff_sh[HI0];  // topk subset of prob-mask
            else {
                unsigned m = k - nxt;           // kept pixels inside bin T
                loss = suff_sh[t + 1] + (float)m * (qf / (float)cnt);
            }
            sloss = loss;
        }
    }
    __syncthreads();

    if (t == 0) {
        g_loss[bc] = sloss;
        __threadfence();
        last = (atomicAdd(&g_done, 1u) == NBC - 1);
    }
    __syncthreads();

    if (last) {                                  // deterministic final reduce
        __shared__ double dred[256];
        dred[t] = (t < NBC) ? (double)g_loss[t] : 0.0;
        __syncthreads();
#pragma unroll
        for (int s = 128; s > 0; s >>= 1) {
            if (t < s) dred[t] += dred[t + s];
            __syncthreads();
        }
        if (t == 0) {
            out[0] = (float)(dred[0] * (1.0 / ((double)QS * (double)NPIX)));
            g_done = 0;                          // reset for next replay
        }
    }
}

// ---------------- launcher ---------------------------------------------------
extern "C" void kernel_launch(void* const* d_in, const int* in_sizes, int n_in,
                              void* d_out, int out_size) {
    const float* pred = (const float*)d_in[0];
    float* out = (float*)d_out;
    (void)in_sizes; (void)n_in; (void)out_size;

    k_compute<<<NBLK_C, 256>>>(pred);
    k_finish<<<NBC, 256>>>(out);
}